// round 4
// baseline (speedup 1.0000x reference)
#include <cuda_runtime.h>
#include <cuda_fp16.h>
#include <cstdint>

// ---------------- problem constants ----------------
#define T_TOK   2048
#define DDIM    1024
#define EXP     8
#define HDIM    4096
#define ROUTED_CAP  6144
#define SHARED_BASE 6144
#define TOTAL_ROWS  8192
#define MTILE   256
#define NMT     (TOTAL_ROWS / MTILE)    // 32
#define ROUTED_MT (ROUTED_CAP / MTILE)  // 24
#define EW_STRIDE (HDIM * DDIM)

// ---------------- device scratch ----------------
__device__ int   g_cnt[EXP];
__device__ int   g_fill[EXP];
__device__ int   g_segstart[EXP];
__device__ int   g_texp[NMT];
__device__ int   g_row_token[TOTAL_ROWS];
__device__ int   g_top_idx[T_TOK * 2];
__device__ float g_top_w[T_TOK * 2];
__device__ int   g_slot[T_TOK * 2];
__device__ __align__(16) __half g_xh[(size_t)TOTAL_ROWS * DDIM];
__device__ __align__(16) __half g_w1h[(size_t)(EXP + 1) * EW_STRIDE];
__device__ __align__(16) __half g_w2h[(size_t)(EXP + 1) * EW_STRIDE];
__device__ __align__(16) float  g_b1u[(EXP + 1) * HDIM];
__device__ __align__(16) float  g_b2u[(EXP + 1) * DDIM];
__device__ __align__(16) __half g_h[(size_t)TOTAL_ROWS * HDIM];
__device__ __align__(16) float  g_eo[(size_t)TOTAL_ROWS * DDIM];

// ---------------- helpers ----------------
__device__ __forceinline__ float gelu_exact(float v) {
    return 0.5f * v * (1.0f + erff(v * 0.70710678118654752f));
}

__device__ __forceinline__ uint32_t smem_to_u32(const void* p) {
    uint32_t a;
    asm("{ .reg .u64 t; cvta.to.shared.u64 t, %1; cvt.u32.u64 %0, t; }" : "=r"(a) : "l"(p));
    return a;
}

__device__ __forceinline__ void ldsm_x4(uint32_t* r, uint32_t a) {
    asm volatile("ldmatrix.sync.aligned.m8n8.x4.shared.b16 {%0,%1,%2,%3}, [%4];\n"
                 : "=r"(r[0]), "=r"(r[1]), "=r"(r[2]), "=r"(r[3]) : "r"(a));
}

__device__ __forceinline__ void mma16816(float* c, const uint32_t* a, const uint32_t* b) {
    asm volatile(
        "mma.sync.aligned.m16n8k16.row.col.f32.f16.f16.f32 "
        "{%0,%1,%2,%3}, {%4,%5,%6,%7}, {%8,%9}, {%0,%1,%2,%3};\n"
        : "+f"(c[0]), "+f"(c[1]), "+f"(c[2]), "+f"(c[3])
        : "r"(a[0]), "r"(a[1]), "r"(a[2]), "r"(a[3]), "r"(b[0]), "r"(b[1]));
}

#define CP_ASYNC16(dst_u32, src_ptr) \
    asm volatile("cp.async.cg.shared.global [%0], [%1], 16;" :: "r"(dst_u32), "l"(src_ptr) : "memory")
#define CP_COMMIT() asm volatile("cp.async.commit_group;" ::: "memory")
#define CP_WAIT1()  asm volatile("cp.async.wait_group 1;" ::: "memory")

// ---------------- routing kernels ----------------
__global__ void k_init() {
    int i = blockIdx.x * blockDim.x + threadIdx.x;
    if (i < TOTAL_ROWS)
        g_row_token[i] = (i >= SHARED_BASE) ? (i - SHARED_BASE) : -1;
    if (i < EXP) { g_cnt[i] = 0; g_fill[i] = 0; }
}

__global__ void k_gate(const float* __restrict__ x, const float* __restrict__ Wg,
                       const float* __restrict__ bg, const float* __restrict__ bias) {
    int gwarp = (blockIdx.x * blockDim.x + threadIdx.x) >> 5;
    int lane  = threadIdx.x & 31;
    if (gwarp >= T_TOK) return;
    const float* xr = x + (size_t)gwarp * DDIM;
    float xs[32];
#pragma unroll
    for (int j = 0; j < 32; j++) xs[j] = xr[lane + 32 * j];
    float s[EXP];
#pragma unroll
    for (int e = 0; e < EXP; e++) {
        const float* wr = Wg + e * DDIM;
        float a = 0.f;
#pragma unroll
        for (int j = 0; j < 32; j++) a += xs[j] * wr[lane + 32 * j];
#pragma unroll
        for (int o = 16; o > 0; o >>= 1) a += __shfl_xor_sync(0xffffffffu, a, o);
        s[e] = 1.0f / (1.0f + expf(-(a + bg[e] + bias[e])));
    }
    if (lane == 0) {
        int i0 = 0; float v0 = s[0];
#pragma unroll
        for (int e = 1; e < EXP; e++) if (s[e] > v0) { v0 = s[e]; i0 = e; }
        int i1 = -1; float v1 = -1e30f;
#pragma unroll
        for (int e = 0; e < EXP; e++) if (e != i0 && s[e] > v1) { v1 = s[e]; i1 = e; }
        g_top_idx[2 * gwarp]     = i0; g_top_w[2 * gwarp]     = v0;
        g_top_idx[2 * gwarp + 1] = i1; g_top_w[2 * gwarp + 1] = v1;
        atomicAdd(&g_cnt[i0], 1);
        atomicAdd(&g_cnt[i1], 1);
    }
}

__global__ void k_seg() {
    if (threadIdx.x == 0 && blockIdx.x == 0) {
        int off = 0;
        for (int e = 0; e < EXP; e++) {
            g_segstart[e] = off;
            int tiles = (g_cnt[e] + 255) >> 8;
            for (int i = 0; i < tiles; i++) g_texp[(off >> 8) + i] = e;
            off += tiles << 8;
        }
        for (int t = off >> 8; t < ROUTED_MT; t++) g_texp[t] = -1;
        for (int t = ROUTED_MT; t < NMT; t++)      g_texp[t] = EXP;
    }
}

__global__ void k_scatter() {
    int t = blockIdx.x * blockDim.x + threadIdx.x;
    if (t >= T_TOK) return;
#pragma unroll
    for (int k = 0; k < 2; k++) {
        int e = g_top_idx[2 * t + k];
        int pos = atomicAdd(&g_fill[e], 1);
        int row = g_segstart[e] + pos;
        g_slot[2 * t + k] = row;
        g_row_token[row]  = t;
    }
}

__global__ void k_xh(const float* __restrict__ x) {
    int r = blockIdx.x;
    int c = threadIdx.x * 8;
    int tok = g_row_token[r];
    __half* dst = g_xh + (size_t)r * DDIM + c;
    if (tok < 0) {
        *reinterpret_cast<uint4*>(dst) = make_uint4(0, 0, 0, 0);
        return;
    }
    const float* src = x + (size_t)tok * DDIM + c;
    float4 a = *reinterpret_cast<const float4*>(src);
    float4 b = *reinterpret_cast<const float4*>(src + 4);
    __half2 h0 = __floats2half2_rn(a.x, a.y), h1 = __floats2half2_rn(a.z, a.w);
    __half2 h2 = __floats2half2_rn(b.x, b.y), h3 = __floats2half2_rn(b.z, b.w);
    uint4 o;
    o.x = *reinterpret_cast<uint32_t*>(&h0); o.y = *reinterpret_cast<uint32_t*>(&h1);
    o.z = *reinterpret_cast<uint32_t*>(&h2); o.w = *reinterpret_cast<uint32_t*>(&h3);
    *reinterpret_cast<uint4*>(dst) = o;
}

__global__ void k_cvt(const float* __restrict__ s, __half* __restrict__ d, int n) {
    int i = (blockIdx.x * blockDim.x + threadIdx.x) * 8;
    if (i >= n) return;
    float4 a = *reinterpret_cast<const float4*>(s + i);
    float4 b = *reinterpret_cast<const float4*>(s + i + 4);
    __half2 h0 = __floats2half2_rn(a.x, a.y), h1 = __floats2half2_rn(a.z, a.w);
    __half2 h2 = __floats2half2_rn(b.x, b.y), h3 = __floats2half2_rn(b.z, b.w);
    uint4 o;
    o.x = *reinterpret_cast<uint32_t*>(&h0); o.y = *reinterpret_cast<uint32_t*>(&h1);
    o.z = *reinterpret_cast<uint32_t*>(&h2); o.w = *reinterpret_cast<uint32_t*>(&h3);
    *reinterpret_cast<uint4*>(d + i) = o;
}

__global__ void k_bias(const float* __restrict__ b1, const float* __restrict__ bs1,
                       const float* __restrict__ b2, const float* __restrict__ bs2) {
    int i = blockIdx.x * blockDim.x + threadIdx.x;
    if (i < EXP * HDIM) g_b1u[i] = b1[i];
    if (i < HDIM)       g_b1u[EXP * HDIM + i] = bs1[i];
    if (i < EXP * DDIM) g_b2u[i] = b2[i];
    if (i < DDIM)       g_b2u[EXP * DDIM + i] = bs2[i];
}

// ---------------- fp16 grouped GEMM (mma.sync, 512 threads, K-chunk 64) ----------------
// Tile 256(M) x 128(N). 16 warps: 4(M) x 4(N), 64x32 per warp.
// K-chunk 64 halves. smem/stage: A 256 rows x 144B = 36864, B 128 x 144B = 18432 -> 55296.
// 3 stages = 165888 B dynamic smem.
#define STG     3
#define STGB    55296
#define ROWB    144        // 64 halves + 8 pad = 72 halves = 144 bytes
#define BOFF    36864

template <int KDIM, bool DOGELU>
__global__ __launch_bounds__(512, 1) void k_gemm(
    const __half* __restrict__ A,
    const __half* __restrict__ W,
    const float*  __restrict__ biasU,
    int NTOT)
{
    constexpr int KT = KDIM / 64;
    extern __shared__ char smem[];
    const uint32_t sb = smem_to_u32(smem);

    const int mt = blockIdx.y;
    const int e  = g_texp[mt];
    if (e < 0) return;
    const int row0 = mt * MTILE;
    const int col0 = blockIdx.x * 128;
    const __half* Ab = A + (size_t)row0 * KDIM;
    const __half* Wb = W + (size_t)e * NTOT * KDIM + (size_t)col0 * KDIM;

    const int tid = threadIdx.x, lane = tid & 31, warp = tid >> 5;
    const int wm = warp & 3, wn = warp >> 2;

    // cp.async assignments: A 2048 16B-chunks (4/thr), B 1024 (2/thr)
    uint32_t aoff[4], agl[4], boff[2], bgl[2];
#pragma unroll
    for (int i = 0; i < 4; i++) {
        int l = tid + i * 512;
        int r = l >> 3, c = l & 7;
        agl[i]  = (uint32_t)r * KDIM + c * 8;
        aoff[i] = r * ROWB + c * 16;
    }
#pragma unroll
    for (int i = 0; i < 2; i++) {
        int l = tid + i * 512;
        int r = l >> 3, c = l & 7;
        bgl[i]  = (uint32_t)r * KDIM + c * 8;
        boff[i] = BOFF + r * ROWB + c * 16;
    }

    auto LOAD = [&](int st, int ch) {
        uint32_t base = sb + st * STGB;
        uint32_t koff = ch * 64;
#pragma unroll
        for (int i = 0; i < 4; i++) CP_ASYNC16(base + aoff[i], Ab + agl[i] + koff);
#pragma unroll
        for (int i = 0; i < 2; i++) CP_ASYNC16(base + boff[i], Wb + bgl[i] + koff);
    };

    float acc[4][4][4];
#pragma unroll
    for (int mi = 0; mi < 4; mi++)
#pragma unroll
        for (int ni = 0; ni < 4; ni++)
#pragma unroll
            for (int j = 0; j < 4; j++) acc[mi][ni][j] = 0.f;

    LOAD(0, 0); CP_COMMIT();
    LOAD(1, 1); CP_COMMIT();

    // ldmatrix base addrs (stage-relative)
    uint32_t a_ld[4], b_ld[2];
#pragma unroll
    for (int mi = 0; mi < 4; mi++) {
        int r = wm * 64 + mi * 16 + ((lane >> 3) & 1) * 8 + (lane & 7);
        int cB = (lane >> 4) * 16;                 // byte offset of 8-half group
        a_ld[mi] = sb + r * ROWB + cB;
    }
#pragma unroll
    for (int np = 0; np < 2; np++) {
        int r = wn * 32 + np * 16 + (lane >> 4) * 8 + (lane & 7);
        int cB = ((lane >> 3) & 1) * 16;
        b_ld[np] = sb + BOFF + r * ROWB + cB;
    }

    int st = 0;
#pragma unroll 1
    for (int i = 0; i < KT; i++) {
        CP_WAIT1();
        __syncthreads();
        int j = i + 2;
        if (j < KT) {
            int nst = st + 2; if (nst >= STG) nst -= STG;
            LOAD(nst, j);
        }
        CP_COMMIT();

        uint32_t so = st * STGB;
#pragma unroll
        for (int ks = 0; ks < 4; ks++) {          // 4 x 16-K steps
            uint32_t kb = so + ks * 32;           // 16 halves = 32 bytes
            uint32_t af[4][4], bf[4][2];
#pragma unroll
            for (int mi = 0; mi < 4; mi++) ldsm_x4(af[mi], a_ld[mi] + kb);
#pragma unroll
            for (int np = 0; np < 2; np++) {
                uint32_t t4[4];
                ldsm_x4(t4, b_ld[np] + kb);
                bf[np * 2][0] = t4[0]; bf[np * 2][1] = t4[1];
                bf[np * 2 + 1][0] = t4[2]; bf[np * 2 + 1][1] = t4[3];
            }
#pragma unroll
            for (int mi = 0; mi < 4; mi++)
#pragma unroll
                for (int ni = 0; ni < 4; ni++)
                    mma16816(acc[mi][ni], af[mi], bf[ni]);
        }
        if (++st == STG) st = 0;
    }

    // epilogue
    const float* bias = biasU + e * NTOT;
#pragma unroll
    for (int mi = 0; mi < 4; mi++) {
#pragma unroll
        for (int ni = 0; ni < 4; ni++) {
            int gr = row0 + wm * 64 + mi * 16 + (lane >> 2);
            int gc = col0 + wn * 32 + ni * 8 + (lane & 3) * 2;
            float b0 = bias[gc], b1v = bias[gc + 1];
            if (DOGELU) {
                float v0 = gelu_exact(acc[mi][ni][0] + b0);
                float v1 = gelu_exact(acc[mi][ni][1] + b1v);
                *reinterpret_cast<__half2*>(&g_h[(size_t)gr * HDIM + gc]) =
                    __floats2half2_rn(v0, v1);
                float v2 = gelu_exact(acc[mi][ni][2] + b0);
                float v3 = gelu_exact(acc[mi][ni][3] + b1v);
                *reinterpret_cast<__half2*>(&g_h[(size_t)(gr + 8) * HDIM + gc]) =
                    __floats2half2_rn(v2, v3);
            } else {
                float2 v01 = make_float2(acc[mi][ni][0] + b0, acc[mi][ni][1] + b1v);
                float2 v23 = make_float2(acc[mi][ni][2] + b0, acc[mi][ni][3] + b1v);
                *reinterpret_cast<float2*>(&g_eo[(size_t)gr * DDIM + gc]) = v01;
                *reinterpret_cast<float2*>(&g_eo[(size_t)(gr + 8) * DDIM + gc]) = v23;
            }
        }
    }
}

// ---------------- combine ----------------
__global__ void k_combine(float* __restrict__ out) {
    int i = blockIdx.x * blockDim.x + threadIdx.x;
    if (i >= T_TOK * DDIM) return;
    int t = i >> 10;
    int d = i & (DDIM - 1);
    float v = g_eo[(size_t)(SHARED_BASE + t) * DDIM + d];
    v += g_top_w[2 * t]     * g_eo[(size_t)g_slot[2 * t]     * DDIM + d];
    v += g_top_w[2 * t + 1] * g_eo[(size_t)g_slot[2 * t + 1] * DDIM + d];
    out[i] = v;
}

// ---------------- launch ----------------
#define GEMM_SMEM (STG * STGB)   // 165888

extern "C" void kernel_launch(void* const* d_in, const int* in_sizes, int n_in,
                              void* d_out, int out_size) {
    const float* x    = (const float*)d_in[0];
    const float* Wg   = (const float*)d_in[1];
    const float* bg   = (const float*)d_in[2];
    const float* bias = (const float*)d_in[3];
    const float* W1   = (const float*)d_in[4];
    const float* b1   = (const float*)d_in[5];
    const float* W2   = (const float*)d_in[6];
    const float* b2   = (const float*)d_in[7];
    const float* Ws1  = (const float*)d_in[8];
    const float* bs1  = (const float*)d_in[9];
    const float* Ws2  = (const float*)d_in[10];
    const float* bs2  = (const float*)d_in[11];
    float* out = (float*)d_out;

    static bool attr_set = false;
    if (!attr_set) {
        cudaFuncSetAttribute(k_gemm<DDIM, true>,
                             cudaFuncAttributeMaxDynamicSharedMemorySize, GEMM_SMEM);
        cudaFuncSetAttribute(k_gemm<HDIM, false>,
                             cudaFuncAttributeMaxDynamicSharedMemorySize, GEMM_SMEM);
        attr_set = true;
    }

    __half* w1h; __half* w2h; __half* xh; __half* hh; float* b1u; float* b2u;
    cudaGetSymbolAddress((void**)&w1h, g_w1h);
    cudaGetSymbolAddress((void**)&w2h, g_w2h);
    cudaGetSymbolAddress((void**)&xh,  g_xh);
    cudaGetSymbolAddress((void**)&hh,  g_h);
    cudaGetSymbolAddress((void**)&b1u, g_b1u);
    cudaGetSymbolAddress((void**)&b2u, g_b2u);

    k_init<<<TOTAL_ROWS / 256, 256>>>();
    k_gate<<<T_TOK * 32 / 256, 256>>>(x, Wg, bg, bias);
    k_seg<<<1, 32>>>();
    k_scatter<<<T_TOK / 256, 256>>>();
    k_xh<<<TOTAL_ROWS, 128>>>(x);
    k_cvt<<<EXP * EW_STRIDE / 8 / 256, 256>>>(W1,  w1h,                           EXP * EW_STRIDE);
    k_cvt<<<EW_STRIDE / 8 / 256,       256>>>(Ws1, w1h + (size_t)EXP * EW_STRIDE, EW_STRIDE);
    k_cvt<<<EXP * EW_STRIDE / 8 / 256, 256>>>(W2,  w2h,                           EXP * EW_STRIDE);
    k_cvt<<<EW_STRIDE / 8 / 256,       256>>>(Ws2, w2h + (size_t)EXP * EW_STRIDE, EW_STRIDE);
    k_bias<<<EXP * HDIM / 256, 256>>>(b1, bs1, b2, bs2);

    k_gemm<DDIM, true ><<<dim3(HDIM / 128, NMT), 512, GEMM_SMEM>>>(xh, w1h, b1u, HDIM);
    k_gemm<HDIM, false><<<dim3(DDIM / 128, NMT), 512, GEMM_SMEM>>>(hh, w2h, b2u, DDIM);

    k_combine<<<T_TOK * DDIM / 256, 256>>>(out);
}

// round 6
// speedup vs baseline: 1.2810x; 1.2810x over previous
#include <cuda_runtime.h>
#include <cuda_fp16.h>
#include <cstdint>

// ---------------- problem constants ----------------
#define T_TOK   2048
#define DDIM    1024
#define EXP     8
#define HDIM    4096
#define ROUTED_CAP  6144
#define SHARED_BASE 6144
#define TOTAL_ROWS  8192
#define MTILE   256
#define NMT     (TOTAL_ROWS / MTILE)    // 32
#define ROUTED_MT (ROUTED_CAP / MTILE)  // 24
#define EW_STRIDE (HDIM * DDIM)

// ---------------- device scratch ----------------
__device__ int   g_cnt[EXP];
__device__ int   g_fill[EXP];
__device__ int   g_segstart[EXP];
__device__ int   g_texp[NMT];
__device__ int   g_row_token[TOTAL_ROWS];
__device__ int   g_top_idx[T_TOK * 2];
__device__ float g_top_w[T_TOK * 2];
__device__ int   g_slot[T_TOK * 2];
__device__ __align__(16) __half g_xh[(size_t)TOTAL_ROWS * DDIM];
__device__ __align__(16) __half g_w1h[(size_t)(EXP + 1) * EW_STRIDE];
__device__ __align__(16) __half g_w2h[(size_t)(EXP + 1) * EW_STRIDE];
__device__ __align__(16) float  g_b1u[(EXP + 1) * HDIM];
__device__ __align__(16) float  g_b2u[(EXP + 1) * DDIM];
__device__ __align__(16) __half g_h[(size_t)TOTAL_ROWS * HDIM];
__device__ __align__(16) float  g_eo[(size_t)TOTAL_ROWS * DDIM];

// ---------------- helpers ----------------
__device__ __forceinline__ float gelu_exact(float v) {
    return 0.5f * v * (1.0f + erff(v * 0.70710678118654752f));
}

__device__ __forceinline__ uint32_t smem_to_u32(const void* p) {
    uint32_t a;
    asm("{ .reg .u64 t; cvta.to.shared.u64 t, %1; cvt.u32.u64 %0, t; }" : "=r"(a) : "l"(p));
    return a;
}

__device__ __forceinline__ void ldsm_x4(uint32_t* r, uint32_t a) {
    asm volatile("ldmatrix.sync.aligned.m8n8.x4.shared.b16 {%0,%1,%2,%3}, [%4];\n"
                 : "=r"(r[0]), "=r"(r[1]), "=r"(r[2]), "=r"(r[3]) : "r"(a));
}

__device__ __forceinline__ void mma16816(float* c, const uint32_t* a, const uint32_t* b) {
    asm volatile(
        "mma.sync.aligned.m16n8k16.row.col.f32.f16.f16.f32 "
        "{%0,%1,%2,%3}, {%4,%5,%6,%7}, {%8,%9}, {%0,%1,%2,%3};\n"
        : "+f"(c[0]), "+f"(c[1]), "+f"(c[2]), "+f"(c[3])
        : "r"(a[0]), "r"(a[1]), "r"(a[2]), "r"(a[3]), "r"(b[0]), "r"(b[1]));
}

#define CP_ASYNC16(dst_u32, src_ptr) \
    asm volatile("cp.async.cg.shared.global [%0], [%1], 16;" :: "r"(dst_u32), "l"(src_ptr) : "memory")
#define CP_COMMIT() asm volatile("cp.async.commit_group;" ::: "memory")
#define CP_WAIT3()  asm volatile("cp.async.wait_group 3;" ::: "memory")

// ---------------- routing kernels ----------------
__global__ void k_init() {
    int i = blockIdx.x * blockDim.x + threadIdx.x;
    if (i < TOTAL_ROWS)
        g_row_token[i] = (i >= SHARED_BASE) ? (i - SHARED_BASE) : -1;
    if (i < EXP) { g_cnt[i] = 0; g_fill[i] = 0; }
}

__global__ void k_gate(const float* __restrict__ x, const float* __restrict__ Wg,
                       const float* __restrict__ bg, const float* __restrict__ bias) {
    int gwarp = (blockIdx.x * blockDim.x + threadIdx.x) >> 5;
    int lane  = threadIdx.x & 31;
    if (gwarp >= T_TOK) return;
    const float* xr = x + (size_t)gwarp * DDIM;
    float xs[32];
#pragma unroll
    for (int j = 0; j < 32; j++) xs[j] = xr[lane + 32 * j];
    float s[EXP];
#pragma unroll
    for (int e = 0; e < EXP; e++) {
        const float* wr = Wg + e * DDIM;
        float a = 0.f;
#pragma unroll
        for (int j = 0; j < 32; j++) a += xs[j] * wr[lane + 32 * j];
#pragma unroll
        for (int o = 16; o > 0; o >>= 1) a += __shfl_xor_sync(0xffffffffu, a, o);
        s[e] = 1.0f / (1.0f + expf(-(a + bg[e] + bias[e])));
    }
    if (lane == 0) {
        int i0 = 0; float v0 = s[0];
#pragma unroll
        for (int e = 1; e < EXP; e++) if (s[e] > v0) { v0 = s[e]; i0 = e; }
        int i1 = -1; float v1 = -1e30f;
#pragma unroll
        for (int e = 0; e < EXP; e++) if (e != i0 && s[e] > v1) { v1 = s[e]; i1 = e; }
        g_top_idx[2 * gwarp]     = i0; g_top_w[2 * gwarp]     = v0;
        g_top_idx[2 * gwarp + 1] = i1; g_top_w[2 * gwarp + 1] = v1;
        atomicAdd(&g_cnt[i0], 1);
        atomicAdd(&g_cnt[i1], 1);
    }
}

__global__ void k_seg() {
    if (threadIdx.x == 0 && blockIdx.x == 0) {
        int off = 0;
        for (int e = 0; e < EXP; e++) {
            g_segstart[e] = off;
            int tiles = (g_cnt[e] + 255) >> 8;
            for (int i = 0; i < tiles; i++) g_texp[(off >> 8) + i] = e;
            off += tiles << 8;
        }
        for (int t = off >> 8; t < ROUTED_MT; t++) g_texp[t] = -1;
        for (int t = ROUTED_MT; t < NMT; t++)      g_texp[t] = EXP;
    }
}

__global__ void k_scatter() {
    int t = blockIdx.x * blockDim.x + threadIdx.x;
    if (t >= T_TOK) return;
#pragma unroll
    for (int k = 0; k < 2; k++) {
        int e = g_top_idx[2 * t + k];
        int pos = atomicAdd(&g_fill[e], 1);
        int row = g_segstart[e] + pos;
        g_slot[2 * t + k] = row;
        g_row_token[row]  = t;
    }
}

__global__ void k_xh(const float* __restrict__ x) {
    int r = blockIdx.x;
    int c = threadIdx.x * 8;
    int tok = g_row_token[r];
    __half* dst = g_xh + (size_t)r * DDIM + c;
    if (tok < 0) {
        *reinterpret_cast<uint4*>(dst) = make_uint4(0, 0, 0, 0);
        return;
    }
    const float* src = x + (size_t)tok * DDIM + c;
    float4 a = *reinterpret_cast<const float4*>(src);
    float4 b = *reinterpret_cast<const float4*>(src + 4);
    __half2 h0 = __floats2half2_rn(a.x, a.y), h1 = __floats2half2_rn(a.z, a.w);
    __half2 h2 = __floats2half2_rn(b.x, b.y), h3 = __floats2half2_rn(b.z, b.w);
    uint4 o;
    o.x = *reinterpret_cast<uint32_t*>(&h0); o.y = *reinterpret_cast<uint32_t*>(&h1);
    o.z = *reinterpret_cast<uint32_t*>(&h2); o.w = *reinterpret_cast<uint32_t*>(&h3);
    *reinterpret_cast<uint4*>(dst) = o;
}

__global__ void k_cvt(const float* __restrict__ s, __half* __restrict__ d, int n) {
    int i = (blockIdx.x * blockDim.x + threadIdx.x) * 8;
    if (i >= n) return;
    float4 a = *reinterpret_cast<const float4*>(s + i);
    float4 b = *reinterpret_cast<const float4*>(s + i + 4);
    __half2 h0 = __floats2half2_rn(a.x, a.y), h1 = __floats2half2_rn(a.z, a.w);
    __half2 h2 = __floats2half2_rn(b.x, b.y), h3 = __floats2half2_rn(b.z, b.w);
    uint4 o;
    o.x = *reinterpret_cast<uint32_t*>(&h0); o.y = *reinterpret_cast<uint32_t*>(&h1);
    o.z = *reinterpret_cast<uint32_t*>(&h2); o.w = *reinterpret_cast<uint32_t*>(&h3);
    *reinterpret_cast<uint4*>(d + i) = o;
}

__global__ void k_bias(const float* __restrict__ b1, const float* __restrict__ bs1,
                       const float* __restrict__ b2, const float* __restrict__ bs2) {
    int i = blockIdx.x * blockDim.x + threadIdx.x;
    if (i < EXP * HDIM) g_b1u[i] = b1[i];
    if (i < HDIM)       g_b1u[EXP * HDIM + i] = bs1[i];
    if (i < EXP * DDIM) g_b2u[i] = b2[i];
    if (i < DDIM)       g_b2u[EXP * DDIM + i] = bs2[i];
}

// ---------------- fp16 grouped GEMM (mma.sync, 5-stage cp.async) ----------------
// Tile 256(M) x 128(N), K-chunk 32. 8 warps: 4(M) x 2(N), 64x64 per warp.
// smem per stage: A 256x40 halves (20480B) + B 128x40 halves (10240B) = 30720B.
// 5 stages = 153600B dynamic smem. Fragments double-buffered in registers.
#define STG   5
#define STGB  30720
#define A_PAD 40

template <int KDIM, bool DOGELU>
__global__ __launch_bounds__(256, 1) void k_gemm(
    const __half* __restrict__ A,      // [TOTAL_ROWS, KDIM] fp16
    const __half* __restrict__ W,      // [(EXP+1), NTOT, KDIM] fp16
    const float*  __restrict__ biasU,  // [(EXP+1), NTOT]
    int NTOT)
{
    constexpr int KT = KDIM / 32;
    extern __shared__ char smem[];
    const uint32_t sb = smem_to_u32(smem);

    const int mt = blockIdx.y;
    const int e  = g_texp[mt];
    if (e < 0) return;
    const int row0 = mt * MTILE;
    const int col0 = blockIdx.x * 128;
    const __half* Wb = W + (size_t)e * NTOT * KDIM;

    const int tid = threadIdx.x, lane = tid & 31, warp = tid >> 5;
    const int wm = warp >> 1, wn = warp & 1;

    // per-thread cp.async assignments
    const __half* asrc[4]; uint32_t aoff[4];
    const __half* bsrc[2]; uint32_t boff[2];
#pragma unroll
    for (int i = 0; i < 4; i++) {
        int l = tid + i * 256;            // 0..1023
        int r = l >> 2, c8 = l & 3;       // r 0..255, 4 x 16B chunks
        asrc[i] = A + (size_t)(row0 + r) * KDIM + c8 * 8;
        aoff[i] = r * (A_PAD * 2) + c8 * 16;
    }
#pragma unroll
    for (int i = 0; i < 2; i++) {
        int l = tid + i * 256;            // 0..511
        int r = l >> 2, c8 = l & 3;       // r 0..127
        bsrc[i] = Wb + (size_t)(col0 + r) * KDIM + c8 * 8;
        boff[i] = 20480 + r * (A_PAD * 2) + c8 * 16;
    }

    auto LOAD = [&](int st, int ch) {
        uint32_t base = sb + st * STGB;
        int koff = ch * 32;
#pragma unroll
        for (int i = 0; i < 4; i++) CP_ASYNC16(base + aoff[i], asrc[i] + koff);
#pragma unroll
        for (int i = 0; i < 2; i++) CP_ASYNC16(base + boff[i], bsrc[i] + koff);
    };

    float acc[4][8][4];
#pragma unroll
    for (int mi = 0; mi < 4; mi++)
#pragma unroll
        for (int ni = 0; ni < 8; ni++)
#pragma unroll
            for (int j = 0; j < 4; j++) acc[mi][ni][j] = 0.f;

    // prologue: 4 chunks in flight
#pragma unroll
    for (int c = 0; c < STG - 1; c++) { LOAD(c, c); CP_COMMIT(); }

    // ldmatrix base addrs (stage-relative)
    uint32_t a_ld[4], b_ld[4];
#pragma unroll
    for (int mi = 0; mi < 4; mi++) {
        int r = wm * 64 + mi * 16 + ((lane >> 3) & 1) * 8 + (lane & 7);
        int c = (lane >> 4) * 8;
        a_ld[mi] = sb + r * (A_PAD * 2) + c * 2;
    }
#pragma unroll
    for (int np = 0; np < 4; np++) {
        int r = wn * 64 + np * 16 + (lane >> 4) * 8 + (lane & 7);
        int c = ((lane >> 3) & 1) * 8;
        b_ld[np] = sb + 20480 + r * (A_PAD * 2) + c * 2;
    }

    int st = 0;
#pragma unroll 1
    for (int i = 0; i < KT; i++) {
        CP_WAIT3();
        __syncthreads();
        int j = i + STG - 1;
        if (j < KT) {
            int nst = st + STG - 1; if (nst >= STG) nst -= STG;
            LOAD(nst, j);
        }
        CP_COMMIT();

        uint32_t so = st * STGB;
        // front-load both k16 steps' fragments (double-buffered), then MMA streams
        uint32_t af[2][4][4], bf[2][8][2];
#pragma unroll
        for (int ks = 0; ks < 2; ks++) {
            uint32_t kb = so + ks * 32;
#pragma unroll
            for (int mi = 0; mi < 4; mi++) ldsm_x4(af[ks][mi], a_ld[mi] + kb);
#pragma unroll
            for (int np = 0; np < 4; np++) {
                uint32_t t4[4];
                ldsm_x4(t4, b_ld[np] + kb);
                bf[ks][np * 2][0] = t4[0]; bf[ks][np * 2][1] = t4[1];
                bf[ks][np * 2 + 1][0] = t4[2]; bf[ks][np * 2 + 1][1] = t4[3];
            }
        }
#pragma unroll
        for (int ks = 0; ks < 2; ks++)
#pragma unroll
            for (int mi = 0; mi < 4; mi++)
#pragma unroll
                for (int ni = 0; ni < 8; ni++)
                    mma16816(acc[mi][ni], af[ks][mi], bf[ks][ni]);

        if (++st == STG) st = 0;
    }

    // epilogue
    const float* bias = biasU + e * NTOT;
#pragma unroll
    for (int mi = 0; mi < 4; mi++) {
#pragma unroll
        for (int ni = 0; ni < 8; ni++) {
            int gr = row0 + wm * 64 + mi * 16 + (lane >> 2);
            int gc = col0 + wn * 64 + ni * 8 + (lane & 3) * 2;
            float b0 = bias[gc], b1v = bias[gc + 1];
            if (DOGELU) {
                float v0 = gelu_exact(acc[mi][ni][0] + b0);
                float v1 = gelu_exact(acc[mi][ni][1] + b1v);
                *reinterpret_cast<__half2*>(&g_h[(size_t)gr * HDIM + gc]) =
                    __floats2half2_rn(v0, v1);
                float v2 = gelu_exact(acc[mi][ni][2] + b0);
                float v3 = gelu_exact(acc[mi][ni][3] + b1v);
                *reinterpret_cast<__half2*>(&g_h[(size_t)(gr + 8) * HDIM + gc]) =
                    __floats2half2_rn(v2, v3);
            } else {
                float2 v01 = make_float2(acc[mi][ni][0] + b0, acc[mi][ni][1] + b1v);
                float2 v23 = make_float2(acc[mi][ni][2] + b0, acc[mi][ni][3] + b1v);
                *reinterpret_cast<float2*>(&g_eo[(size_t)gr * DDIM + gc]) = v01;
                *reinterpret_cast<float2*>(&g_eo[(size_t)(gr + 8) * DDIM + gc]) = v23;
            }
        }
    }
}

// ---------------- combine ----------------
__global__ void k_combine(float* __restrict__ out) {
    int i = blockIdx.x * blockDim.x + threadIdx.x;
    if (i >= T_TOK * DDIM) return;
    int t = i >> 10;
    int d = i & (DDIM - 1);
    float v = g_eo[(size_t)(SHARED_BASE + t) * DDIM + d];
    v += g_top_w[2 * t]     * g_eo[(size_t)g_slot[2 * t]     * DDIM + d];
    v += g_top_w[2 * t + 1] * g_eo[(size_t)g_slot[2 * t + 1] * DDIM + d];
    out[i] = v;
}

// ---------------- launch ----------------
#define GEMM_SMEM (STG * STGB)   // 153600

extern "C" void kernel_launch(void* const* d_in, const int* in_sizes, int n_in,
                              void* d_out, int out_size) {
    const float* x    = (const float*)d_in[0];
    const float* Wg   = (const float*)d_in[1];
    const float* bg   = (const float*)d_in[2];
    const float* bias = (const float*)d_in[3];
    const float* W1   = (const float*)d_in[4];
    const float* b1   = (const float*)d_in[5];
    const float* W2   = (const float*)d_in[6];
    const float* b2   = (const float*)d_in[7];
    const float* Ws1  = (const float*)d_in[8];
    const float* bs1  = (const float*)d_in[9];
    const float* Ws2  = (const float*)d_in[10];
    const float* bs2  = (const float*)d_in[11];
    float* out = (float*)d_out;

    static bool attr_set = false;
    if (!attr_set) {
        cudaFuncSetAttribute(k_gemm<DDIM, true>,
                             cudaFuncAttributeMaxDynamicSharedMemorySize, GEMM_SMEM);
        cudaFuncSetAttribute(k_gemm<HDIM, false>,
                             cudaFuncAttributeMaxDynamicSharedMemorySize, GEMM_SMEM);
        attr_set = true;
    }

    __half* w1h; __half* w2h; __half* xh; __half* hh; float* b1u; float* b2u;
    cudaGetSymbolAddress((void**)&w1h, g_w1h);
    cudaGetSymbolAddress((void**)&w2h, g_w2h);
    cudaGetSymbolAddress((void**)&xh,  g_xh);
    cudaGetSymbolAddress((void**)&hh,  g_h);
    cudaGetSymbolAddress((void**)&b1u, g_b1u);
    cudaGetSymbolAddress((void**)&b2u, g_b2u);

    k_init<<<TOTAL_ROWS / 256, 256>>>();
    k_gate<<<T_TOK * 32 / 256, 256>>>(x, Wg, bg, bias);
    k_seg<<<1, 32>>>();
    k_scatter<<<T_TOK / 256, 256>>>();
    k_xh<<<TOTAL_ROWS, 128>>>(x);
    k_cvt<<<EXP * EW_STRIDE / 8 / 256, 256>>>(W1,  w1h,                           EXP * EW_STRIDE);
    k_cvt<<<EW_STRIDE / 8 / 256,       256>>>(Ws1, w1h + (size_t)EXP * EW_STRIDE, EW_STRIDE);
    k_cvt<<<EXP * EW_STRIDE / 8 / 256, 256>>>(W2,  w2h,                           EXP * EW_STRIDE);
    k_cvt<<<EW_STRIDE / 8 / 256,       256>>>(Ws2, w2h + (size_t)EXP * EW_STRIDE, EW_STRIDE);
    k_bias<<<EXP * HDIM / 256, 256>>>(b1, bs1, b2, bs2);

    k_gemm<DDIM, true ><<<dim3(HDIM / 128, NMT), 256, GEMM_SMEM>>>(xh, w1h, b1u, HDIM);
    k_gemm<HDIM, false><<<dim3(DDIM / 128, NMT), 256, GEMM_SMEM>>>(hh, w2h, b2u, DDIM);

    k_combine<<<T_TOK * DDIM / 256, 256>>>(out);
}

// round 7
// speedup vs baseline: 1.7376x; 1.3564x over previous
#include <cuda_runtime.h>
#include <cuda_fp16.h>
#include <cstdint>

// ---------------- problem constants ----------------
#define T_TOK   2048
#define DDIM    1024
#define EXP     8
#define HDIM    4096
#define MT      128                       // M-tile rows
#define ROUTED_CAP  5120                  // 4096 + 8*128 worst-case pad
#define SHARED_BASE 5120
#define TOTAL_ROWS  7168
#define NMT     (TOTAL_ROWS / MT)         // 56
#define ROUTED_MT (ROUTED_CAP / MT)       // 40
#define EW_STRIDE (HDIM * DDIM)
#define PGRID   304                       // persistent CTAs (2 per SM)

// ---------------- device scratch ----------------
__device__ int   g_cnt[EXP];
__device__ int   g_fill[EXP];
__device__ int   g_segstart[EXP];
__device__ int   g_texp[NMT];
__device__ int   g_vt[NMT];
__device__ int   g_nv;
__device__ int   g_row_token[TOTAL_ROWS];
__device__ int   g_top_idx[T_TOK * 2];
__device__ float g_top_w[T_TOK * 2];
__device__ int   g_slot[T_TOK * 2];
__device__ __align__(16) __half g_xh[(size_t)TOTAL_ROWS * DDIM];
__device__ __align__(16) __half g_w1h[(size_t)(EXP + 1) * EW_STRIDE];
__device__ __align__(16) __half g_w2h[(size_t)(EXP + 1) * EW_STRIDE];
__device__ __align__(16) float  g_b1u[(EXP + 1) * HDIM];
__device__ __align__(16) float  g_b2u[(EXP + 1) * DDIM];
__device__ __align__(16) __half g_h[(size_t)TOTAL_ROWS * HDIM];
__device__ __align__(16) float  g_eo[2 * (size_t)TOTAL_ROWS * DDIM];   // split-K partials

// ---------------- helpers ----------------
__device__ __forceinline__ float gelu_exact(float v) {
    return 0.5f * v * (1.0f + erff(v * 0.70710678118654752f));
}

__device__ __forceinline__ uint32_t smem_to_u32(const void* p) {
    uint32_t a;
    asm("{ .reg .u64 t; cvta.to.shared.u64 t, %1; cvt.u32.u64 %0, t; }" : "=r"(a) : "l"(p));
    return a;
}

__device__ __forceinline__ void ldsm_x4(uint32_t* r, uint32_t a) {
    asm volatile("ldmatrix.sync.aligned.m8n8.x4.shared.b16 {%0,%1,%2,%3}, [%4];\n"
                 : "=r"(r[0]), "=r"(r[1]), "=r"(r[2]), "=r"(r[3]) : "r"(a));
}

__device__ __forceinline__ void mma16816(float* c, const uint32_t* a, const uint32_t* b) {
    asm volatile(
        "mma.sync.aligned.m16n8k16.row.col.f32.f16.f16.f32 "
        "{%0,%1,%2,%3}, {%4,%5,%6,%7}, {%8,%9}, {%0,%1,%2,%3};\n"
        : "+f"(c[0]), "+f"(c[1]), "+f"(c[2]), "+f"(c[3])
        : "r"(a[0]), "r"(a[1]), "r"(a[2]), "r"(a[3]), "r"(b[0]), "r"(b[1]));
}

#define CP_ASYNC16(dst_u32, src_ptr) \
    asm volatile("cp.async.cg.shared.global [%0], [%1], 16;" :: "r"(dst_u32), "l"(src_ptr) : "memory")
#define CP_COMMIT() asm volatile("cp.async.commit_group;" ::: "memory")
#define CP_WAIT2()  asm volatile("cp.async.wait_group 2;" ::: "memory")

// ---------------- routing kernels ----------------
__global__ void k_init() {
    int i = blockIdx.x * blockDim.x + threadIdx.x;
    if (i < TOTAL_ROWS)
        g_row_token[i] = (i >= SHARED_BASE) ? (i - SHARED_BASE) : -1;
    if (i < EXP) { g_cnt[i] = 0; g_fill[i] = 0; }
}

__global__ void k_gate(const float* __restrict__ x, const float* __restrict__ Wg,
                       const float* __restrict__ bg, const float* __restrict__ bias) {
    int gwarp = (blockIdx.x * blockDim.x + threadIdx.x) >> 5;
    int lane  = threadIdx.x & 31;
    if (gwarp >= T_TOK) return;
    const float* xr = x + (size_t)gwarp * DDIM;
    float xs[32];
#pragma unroll
    for (int j = 0; j < 32; j++) xs[j] = xr[lane + 32 * j];
    float s[EXP];
#pragma unroll
    for (int e = 0; e < EXP; e++) {
        const float* wr = Wg + e * DDIM;
        float a = 0.f;
#pragma unroll
        for (int j = 0; j < 32; j++) a += xs[j] * wr[lane + 32 * j];
#pragma unroll
        for (int o = 16; o > 0; o >>= 1) a += __shfl_xor_sync(0xffffffffu, a, o);
        s[e] = 1.0f / (1.0f + expf(-(a + bg[e] + bias[e])));
    }
    if (lane == 0) {
        int i0 = 0; float v0 = s[0];
#pragma unroll
        for (int e = 1; e < EXP; e++) if (s[e] > v0) { v0 = s[e]; i0 = e; }
        int i1 = -1; float v1 = -1e30f;
#pragma unroll
        for (int e = 0; e < EXP; e++) if (e != i0 && s[e] > v1) { v1 = s[e]; i1 = e; }
        g_top_idx[2 * gwarp]     = i0; g_top_w[2 * gwarp]     = v0;
        g_top_idx[2 * gwarp + 1] = i1; g_top_w[2 * gwarp + 1] = v1;
        atomicAdd(&g_cnt[i0], 1);
        atomicAdd(&g_cnt[i1], 1);
    }
}

__global__ void k_seg() {
    if (threadIdx.x == 0 && blockIdx.x == 0) {
        int off = 0, nv = 0;
        for (int e = 0; e < EXP; e++) {
            g_segstart[e] = off;
            int tiles = (g_cnt[e] + MT - 1) / MT;
            for (int i = 0; i < tiles; i++) {
                int mt = off / MT + i;
                g_texp[mt] = e;
                g_vt[nv++] = mt;
            }
            off += tiles * MT;
        }
        for (int t = off / MT; t < ROUTED_MT; t++) g_texp[t] = -1;
        for (int t = ROUTED_MT; t < NMT; t++) { g_texp[t] = EXP; g_vt[nv++] = t; }
        g_nv = nv;
    }
}

__global__ void k_scatter() {
    int t = blockIdx.x * blockDim.x + threadIdx.x;
    if (t >= T_TOK) return;
#pragma unroll
    for (int k = 0; k < 2; k++) {
        int e = g_top_idx[2 * t + k];
        int pos = atomicAdd(&g_fill[e], 1);
        int row = g_segstart[e] + pos;
        g_slot[2 * t + k] = row;
        g_row_token[row]  = t;
    }
}

__global__ void k_xh(const float* __restrict__ x) {
    int r = blockIdx.x;
    int c = threadIdx.x * 8;
    int tok = g_row_token[r];
    __half* dst = g_xh + (size_t)r * DDIM + c;
    if (tok < 0) {
        *reinterpret_cast<uint4*>(dst) = make_uint4(0, 0, 0, 0);
        return;
    }
    const float* src = x + (size_t)tok * DDIM + c;
    float4 a = *reinterpret_cast<const float4*>(src);
    float4 b = *reinterpret_cast<const float4*>(src + 4);
    __half2 h0 = __floats2half2_rn(a.x, a.y), h1 = __floats2half2_rn(a.z, a.w);
    __half2 h2 = __floats2half2_rn(b.x, b.y), h3 = __floats2half2_rn(b.z, b.w);
    uint4 o;
    o.x = *reinterpret_cast<uint32_t*>(&h0); o.y = *reinterpret_cast<uint32_t*>(&h1);
    o.z = *reinterpret_cast<uint32_t*>(&h2); o.w = *reinterpret_cast<uint32_t*>(&h3);
    *reinterpret_cast<uint4*>(dst) = o;
}

__global__ void k_cvt(const float* __restrict__ s, __half* __restrict__ d, int n) {
    int i = (blockIdx.x * blockDim.x + threadIdx.x) * 8;
    if (i >= n) return;
    float4 a = *reinterpret_cast<const float4*>(s + i);
    float4 b = *reinterpret_cast<const float4*>(s + i + 4);
    __half2 h0 = __floats2half2_rn(a.x, a.y), h1 = __floats2half2_rn(a.z, a.w);
    __half2 h2 = __floats2half2_rn(b.x, b.y), h3 = __floats2half2_rn(b.z, b.w);
    uint4 o;
    o.x = *reinterpret_cast<uint32_t*>(&h0); o.y = *reinterpret_cast<uint32_t*>(&h1);
    o.z = *reinterpret_cast<uint32_t*>(&h2); o.w = *reinterpret_cast<uint32_t*>(&h3);
    *reinterpret_cast<uint4*>(d + i) = o;
}

__global__ void k_bias(const float* __restrict__ b1, const float* __restrict__ bs1,
                       const float* __restrict__ b2, const float* __restrict__ bs2) {
    int i = blockIdx.x * blockDim.x + threadIdx.x;
    if (i < EXP * HDIM) g_b1u[i] = b1[i];
    if (i < HDIM)       g_b1u[EXP * HDIM + i] = bs1[i];
    if (i < EXP * DDIM) g_b2u[i] = b2[i];
    if (i < DDIM)       g_b2u[EXP * DDIM + i] = bs2[i];
}

// ---------------- persistent fp16 grouped GEMM ----------------
// CTA tile 128(M) x 128(N), 128 threads = 4 warps (2M x 2N of 64x64).
// K-chunk 32 halves, 4-stage cp.async. smem/stage: A 128x80B + B 128x80B = 20480B.
// 4 stages = 81920B -> 2 CTAs/SM. Persistent item loop over (valid_tile, ncol, kpart).
#define STG   4
#define STGB  20480
#define BOFFS 10240
#define GEMM_SMEM (STG * STGB)   // 81920

template <int KDIM, int NT, int NPART, bool DOGELU>
__global__ __launch_bounds__(128, 2) void k_gemm(
    const __half* __restrict__ A,      // [TOTAL_ROWS, KDIM] fp16
    const __half* __restrict__ W,      // [(EXP+1), NTOT, KDIM] fp16
    const float*  __restrict__ biasU,  // [(EXP+1), NTOT]
    int NTOT)
{
    constexpr int KPART = KDIM / NPART;
    constexpr int KT = KPART / 32;
    extern __shared__ char smem[];
    const uint32_t sb = smem_to_u32(smem);

    const int tid = threadIdx.x, lane = tid & 31, warp = tid >> 5;
    const int wm = warp >> 1, wn = warp & 1;

    // item-independent per-thread offsets
    uint32_t agl[4], aoff[4], bgl[4], boff[4];
#pragma unroll
    for (int i = 0; i < 4; i++) {
        int l = tid + i * 128;            // 0..511
        int r = l >> 2, c8 = l & 3;       // r 0..127, 4 x 16B chunks per row
        agl[i]  = (uint32_t)r * KDIM + c8 * 8;
        aoff[i] = r * 80 + c8 * 16;
        bgl[i]  = agl[i];
        boff[i] = BOFFS + r * 80 + c8 * 16;
    }
    uint32_t a_ld[4], b_ld[4];
#pragma unroll
    for (int mi = 0; mi < 4; mi++) {
        int r = wm * 64 + mi * 16 + ((lane >> 3) & 1) * 8 + (lane & 7);
        int c = (lane >> 4) * 8;
        a_ld[mi] = sb + r * 80 + c * 2;
    }
#pragma unroll
    for (int np = 0; np < 4; np++) {
        int r = wn * 64 + np * 16 + (lane >> 4) * 8 + (lane & 7);
        int c = ((lane >> 3) & 1) * 8;
        b_ld[np] = sb + BOFFS + r * 80 + c * 2;
    }

    const int nv = g_nv;
    const int nitems = nv * NT * NPART;

    for (int it = blockIdx.x; it < nitems; it += gridDim.x) {
        int p  = it % NPART;
        int q  = it / NPART;
        int nt = q % NT;
        int v  = q / NT;
        int mt = g_vt[v];
        int e  = g_texp[mt];
        const int row0 = mt * MT;
        const int col0 = nt * 128;
        const __half* Ab = A + (size_t)row0 * KDIM + p * KPART;
        const __half* Wb = W + (size_t)e * NTOT * KDIM + (size_t)col0 * KDIM + p * KPART;

        float acc[4][8][4];
#pragma unroll
        for (int mi = 0; mi < 4; mi++)
#pragma unroll
            for (int ni = 0; ni < 8; ni++)
#pragma unroll
                for (int j = 0; j < 4; j++) acc[mi][ni][j] = 0.f;

        auto LOAD = [&](int st, int ch) {
            uint32_t base = sb + st * STGB;
            uint32_t koff = ch * 32;
#pragma unroll
            for (int i = 0; i < 4; i++) CP_ASYNC16(base + aoff[i], Ab + agl[i] + koff);
#pragma unroll
            for (int i = 0; i < 4; i++) CP_ASYNC16(base + boff[i], Wb + bgl[i] + koff);
        };

#pragma unroll
        for (int c = 0; c < STG - 1; c++) { LOAD(c, c); CP_COMMIT(); }

#pragma unroll 1
        for (int i = 0; i < KT; i++) {
            CP_WAIT2();
            __syncthreads();
            int j = i + STG - 1;
            if (j < KT) LOAD(j & (STG - 1), j);
            CP_COMMIT();

            uint32_t so = (i & (STG - 1)) * STGB;
#pragma unroll
            for (int ks = 0; ks < 2; ks++) {
                uint32_t kb = so + ks * 32;
                uint32_t af[4][4], bf[8][2];
#pragma unroll
                for (int mi = 0; mi < 4; mi++) ldsm_x4(af[mi], a_ld[mi] + kb);
#pragma unroll
                for (int np = 0; np < 4; np++) {
                    uint32_t t4[4];
                    ldsm_x4(t4, b_ld[np] + kb);
                    bf[np * 2][0] = t4[0]; bf[np * 2][1] = t4[1];
                    bf[np * 2 + 1][0] = t4[2]; bf[np * 2 + 1][1] = t4[3];
                }
#pragma unroll
                for (int mi = 0; mi < 4; mi++)
#pragma unroll
                    for (int ni = 0; ni < 8; ni++)
                        mma16816(acc[mi][ni], af[mi], bf[ni]);
            }
        }

        // epilogue
        const float* bias = biasU + e * NTOT;
        float* eout = g_eo + (size_t)p * TOTAL_ROWS * DDIM;
        bool addb = (p == 0);
#pragma unroll
        for (int mi = 0; mi < 4; mi++) {
#pragma unroll
            for (int ni = 0; ni < 8; ni++) {
                int gr = row0 + wm * 64 + mi * 16 + (lane >> 2);
                int gc = col0 + wn * 64 + ni * 8 + (lane & 3) * 2;
                if (DOGELU) {
                    float b0 = bias[gc], b1v = bias[gc + 1];
                    float v0 = gelu_exact(acc[mi][ni][0] + b0);
                    float v1 = gelu_exact(acc[mi][ni][1] + b1v);
                    *reinterpret_cast<__half2*>(&g_h[(size_t)gr * HDIM + gc]) =
                        __floats2half2_rn(v0, v1);
                    float v2 = gelu_exact(acc[mi][ni][2] + b0);
                    float v3 = gelu_exact(acc[mi][ni][3] + b1v);
                    *reinterpret_cast<__half2*>(&g_h[(size_t)(gr + 8) * HDIM + gc]) =
                        __floats2half2_rn(v2, v3);
                } else {
                    float b0 = addb ? bias[gc] : 0.f;
                    float b1v = addb ? bias[gc + 1] : 0.f;
                    float2 v01 = make_float2(acc[mi][ni][0] + b0, acc[mi][ni][1] + b1v);
                    float2 v23 = make_float2(acc[mi][ni][2] + b0, acc[mi][ni][3] + b1v);
                    *reinterpret_cast<float2*>(&eout[(size_t)gr * DDIM + gc]) = v01;
                    *reinterpret_cast<float2*>(&eout[(size_t)(gr + 8) * DDIM + gc]) = v23;
                }
            }
        }
        // stage safety across items: last chunk used stage (KT-1)&3 == 3 (KT multiple of 4),
        // next prologue writes stages 0..2; max warp drift is one barrier interval. Safe.
    }
}

// ---------------- combine (sums split-K partials) ----------------
__global__ void k_combine(float* __restrict__ out) {
    int i = blockIdx.x * blockDim.x + threadIdx.x;
    if (i >= T_TOK * DDIM) return;
    int t = i >> 10;
    int d = i & (DDIM - 1);
    const float* e0 = g_eo;
    const float* e1 = g_eo + (size_t)TOTAL_ROWS * DDIM;
    size_t sr = (size_t)(SHARED_BASE + t) * DDIM + d;
    size_t s0 = (size_t)g_slot[2 * t]     * DDIM + d;
    size_t s1 = (size_t)g_slot[2 * t + 1] * DDIM + d;
    float v = (e0[sr] + e1[sr]);
    v += g_top_w[2 * t]     * (e0[s0] + e1[s0]);
    v += g_top_w[2 * t + 1] * (e0[s1] + e1[s1]);
    out[i] = v;
}

// ---------------- launch ----------------
extern "C" void kernel_launch(void* const* d_in, const int* in_sizes, int n_in,
                              void* d_out, int out_size) {
    const float* x    = (const float*)d_in[0];
    const float* Wg   = (const float*)d_in[1];
    const float* bg   = (const float*)d_in[2];
    const float* bias = (const float*)d_in[3];
    const float* W1   = (const float*)d_in[4];
    const float* b1   = (const float*)d_in[5];
    const float* W2   = (const float*)d_in[6];
    const float* b2   = (const float*)d_in[7];
    const float* Ws1  = (const float*)d_in[8];
    const float* bs1  = (const float*)d_in[9];
    const float* Ws2  = (const float*)d_in[10];
    const float* bs2  = (const float*)d_in[11];
    float* out = (float*)d_out;

    static bool attr_set = false;
    if (!attr_set) {
        cudaFuncSetAttribute(k_gemm<DDIM, HDIM / 128, 1, true>,
                             cudaFuncAttributeMaxDynamicSharedMemorySize, GEMM_SMEM);
        cudaFuncSetAttribute(k_gemm<HDIM, DDIM / 128, 2, false>,
                             cudaFuncAttributeMaxDynamicSharedMemorySize, GEMM_SMEM);
        attr_set = true;
    }

    __half* w1h; __half* w2h; __half* xh; __half* hh; float* b1u; float* b2u;
    cudaGetSymbolAddress((void**)&w1h, g_w1h);
    cudaGetSymbolAddress((void**)&w2h, g_w2h);
    cudaGetSymbolAddress((void**)&xh,  g_xh);
    cudaGetSymbolAddress((void**)&hh,  g_h);
    cudaGetSymbolAddress((void**)&b1u, g_b1u);
    cudaGetSymbolAddress((void**)&b2u, g_b2u);

    k_init<<<(TOTAL_ROWS + 255) / 256, 256>>>();
    k_gate<<<T_TOK * 32 / 256, 256>>>(x, Wg, bg, bias);
    k_seg<<<1, 32>>>();
    k_scatter<<<T_TOK / 256, 256>>>();
    k_xh<<<TOTAL_ROWS, 128>>>(x);
    k_cvt<<<EXP * EW_STRIDE / 8 / 256, 256>>>(W1,  w1h,                           EXP * EW_STRIDE);
    k_cvt<<<EW_STRIDE / 8 / 256,       256>>>(Ws1, w1h + (size_t)EXP * EW_STRIDE, EW_STRIDE);
    k_cvt<<<EXP * EW_STRIDE / 8 / 256, 256>>>(W2,  w2h,                           EXP * EW_STRIDE);
    k_cvt<<<EW_STRIDE / 8 / 256,       256>>>(Ws2, w2h + (size_t)EXP * EW_STRIDE, EW_STRIDE);
    k_bias<<<EXP * HDIM / 256, 256>>>(b1, bs1, b2, bs2);

    k_gemm<DDIM, HDIM / 128, 1, true ><<<PGRID, 128, GEMM_SMEM>>>(xh, w1h, b1u, HDIM);
    k_gemm<HDIM, DDIM / 128, 2, false><<<PGRID, 128, GEMM_SMEM>>>(hh, w2h, b2u, DDIM);

    k_combine<<<T_TOK * DDIM / 256, 256>>>(out);
}